// round 14
// baseline (speedup 1.0000x reference)
#include <cuda_runtime.h>
#include <cuda_fp16.h>
#include <stdint.h>
#include <math.h>

#define S_DIM  4096
#define IN_DIM 1024
#define NODE_DIM 512
#define NH 8
#define HD 64

// ---------------- scratch (no cudaMalloc allowed) ----------------
__device__ uint16_t g_Ah[S_DIM * IN_DIM];        // emb fp16
__device__ uint16_t g_Wqh[NODE_DIM * IN_DIM];
__device__ uint16_t g_Wkh[NODE_DIM * IN_DIM];
__device__ uint16_t g_Wvh[NODE_DIM * IN_DIM];
__device__ uint16_t g_Woh[NODE_DIM * NODE_DIM];
__device__ uint16_t g_Ch[S_DIM * S_DIM];         // contact fp16
__device__ uint16_t g_Qh[NH * S_DIM * HD];       // [h][s][d] fp16, pre-scaled 0.125*Wc*log2e
__device__ uint16_t g_Kh[NH * S_DIM * HD];       // [h][s][d] fp16
__device__ uint16_t g_Vt[NH * HD * S_DIM];       // [h][d][s] fp16 (transposed)
__device__ uint16_t g_Oh[NH * S_DIM * HD];       // fp16, flat == scrambled [S, H*D]
__device__ float    g_T [S_DIM * NODE_DIM];      // pre-LayerNorm, K-half 0
__device__ float    g_T2[S_DIM * NODE_DIM];      // pre-LayerNorm, K-half 1

// ---------------- helpers ----------------
__device__ __forceinline__ uint32_t cvt_h2(float lo, float hi) {
    uint32_t r;
    asm("cvt.rn.f16x2.f32 %0, %1, %2;" : "=r"(r) : "f"(hi), "f"(lo));
    return r;
}
__device__ __forceinline__ uint32_t hmul2(uint32_t a, uint32_t b) {
    uint32_t r; asm("mul.f16x2 %0, %1, %2;" : "=r"(r) : "r"(a), "r"(b)); return r;
}
__device__ __forceinline__ uint32_t hadd2(uint32_t a, uint32_t b) {
    uint32_t r; asm("add.f16x2 %0, %1, %2;" : "=r"(r) : "r"(a), "r"(b)); return r;
}
__device__ __forceinline__ uint32_t h2ex2(uint32_t a) {
    uint32_t r; asm("ex2.approx.f16x2 %0, %1;" : "=r"(r) : "r"(a)); return r;
}
__device__ __forceinline__ void mma_f16(float* d, const uint32_t* a, const uint32_t* b) {
    asm volatile(
        "mma.sync.aligned.m16n8k16.row.col.f32.f16.f16.f32 "
        "{%0,%1,%2,%3}, {%4,%5,%6,%7}, {%8,%9}, {%0,%1,%2,%3};"
        : "+f"(d[0]), "+f"(d[1]), "+f"(d[2]), "+f"(d[3])
        : "r"(a[0]), "r"(a[1]), "r"(a[2]), "r"(a[3]), "r"(b[0]), "r"(b[1]));
}
__device__ __forceinline__ void mma_f16h(uint32_t* d, const uint32_t* a, const uint32_t* b) {
    asm volatile(
        "mma.sync.aligned.m16n8k16.row.col.f16.f16.f16.f16 "
        "{%0,%1}, {%2,%3,%4,%5}, {%6,%7}, {%0,%1};"
        : "+r"(d[0]), "+r"(d[1])
        : "r"(a[0]), "r"(a[1]), "r"(a[2]), "r"(a[3]), "r"(b[0]), "r"(b[1]));
}
__device__ __forceinline__ void ldsm4(uint32_t* r, const uint16_t* p) {
    uint32_t a = (uint32_t)__cvta_generic_to_shared(p);
    asm volatile("ldmatrix.sync.aligned.m8n8.x4.shared.b16 {%0,%1,%2,%3}, [%4];"
        : "=r"(r[0]), "=r"(r[1]), "=r"(r[2]), "=r"(r[3]) : "r"(a));
}
__device__ __forceinline__ void cp16(uint16_t* dst, const uint16_t* src) {
    uint32_t a = (uint32_t)__cvta_generic_to_shared(dst);
    asm volatile("cp.async.cg.shared.global [%0], [%1], 16;" :: "r"(a), "l"(src));
}
#define CP_COMMIT() asm volatile("cp.async.commit_group;" ::: "memory")
#define CP_WAIT1()  asm volatile("cp.async.wait_group 1;" ::: "memory")
#define CP_WAIT2()  asm volatile("cp.async.wait_group 2;" ::: "memory")

// ---------------- prep: fp32 -> fp16, once (weights, emb, contact) ----------------
__global__ void prep_kernel(const float* __restrict__ emb,
                            const float* __restrict__ Wq,
                            const float* __restrict__ Wk,
                            const float* __restrict__ Wv,
                            const float* __restrict__ Wo,
                            const float* __restrict__ contact)
{
    const int t = blockIdx.x * blockDim.x + threadIdx.x;
    const int stride = gridDim.x * blockDim.x;
    for (int i = t; i < (S_DIM * IN_DIM) / 4; i += stride) {
        float4 v = ((const float4*)emb)[i];
        ((uint2*)g_Ah)[i] = make_uint2(cvt_h2(v.x, v.y), cvt_h2(v.z, v.w));
    }
    for (int i = t; i < (NODE_DIM * IN_DIM) / 4; i += stride) {
        float4 a = ((const float4*)Wq)[i];
        ((uint2*)g_Wqh)[i] = make_uint2(cvt_h2(a.x, a.y), cvt_h2(a.z, a.w));
        float4 b = ((const float4*)Wk)[i];
        ((uint2*)g_Wkh)[i] = make_uint2(cvt_h2(b.x, b.y), cvt_h2(b.z, b.w));
        float4 c = ((const float4*)Wv)[i];
        ((uint2*)g_Wvh)[i] = make_uint2(cvt_h2(c.x, c.y), cvt_h2(c.z, c.w));
    }
    for (int i = t; i < (NODE_DIM * NODE_DIM) / 4; i += stride) {
        float4 v = ((const float4*)Wo)[i];
        ((uint2*)g_Woh)[i] = make_uint2(cvt_h2(v.x, v.y), cvt_h2(v.z, v.w));
    }
    for (int i = t; i < (S_DIM * S_DIM) / 4; i += stride) {
        float4 v = ((const float4*)contact)[i];
        ((uint2*)g_Ch)[i] = make_uint2(cvt_h2(v.x, v.y), cvt_h2(v.z, v.w));
    }
}

// ======================= fp16 HMMA GEMM: 4-stage cp.async pipeline =======================
// CTA 128x128, K-chunk 32, 4 stages. 8 warps 4(M)x2(N); warp tile 32x64.
// Stage block: rows 0..127 = A, rows 128..255 = W.
#define GST 40
#define GSTAGE (256 * GST)                      // u16 per stage
#define GEMM_SMEM (4 * GSTAGE * 2)              // 81,920 B

__device__ __forceinline__ void hmma_loop_16(
    const uint16_t* __restrict__ A, const uint16_t* __restrict__ W, int K,
    int kbeg, int kend, int m0, int n0,
    uint16_t* smg, float acc[2][8][4])
{
    const int tid = threadIdx.x;
    const int wid = tid >> 5, lane = tid & 31;
    const int wm = wid >> 1, wn = wid & 1;
    const int arow = ((lane >> 3) & 1) * 8 + (lane & 7);
    const int acol = ((lane >> 4) & 1) * 8;
    const int brow = ((lane >> 4) & 1) * 8 + (lane & 7);
    const int bcol = ((lane >> 3) & 1) * 8;

    const int nch = (kend - kbeg) >> 5;

    auto cp_chunk = [&](int kc, int s) {
        uint16_t (*stg)[GST] = (uint16_t(*)[GST])(smg + s * GSTAGE);
#pragma unroll
        for (int i = 0; i < 2; i++) {
            int idx = tid + i * 256;                // 512: 128 rows x 4 cp16
            int row = idx >> 2, q = idx & 3;
            cp16(&stg[row][q * 8],       &A[(size_t)(m0 + row) * K + kc + q * 8]);
            cp16(&stg[128 + row][q * 8], &W[(size_t)(n0 + row) * K + kc + q * 8]);
        }
    };

    // prologue: 3 committed groups (some possibly empty)
#pragma unroll
    for (int s = 0; s < 3; s++) {
        if (s < nch) cp_chunk(kbeg + s * 32, s);
        CP_COMMIT();
    }

    for (int c = 0; c < nch; c++) {
        CP_WAIT2();                 // stages 0..c complete (one group committed per iter)
        __syncthreads();
        int nx = c + 3;
        if (nx < nch) cp_chunk(kbeg + nx * 32, nx & 3);
        CP_COMMIT();                // always exactly one group per iteration

        uint16_t (*stg)[GST] = (uint16_t(*)[GST])(smg + (c & 3) * GSTAGE);
#pragma unroll
        for (int kt = 0; kt < 2; kt++) {
            uint32_t ah[2][4];
            ldsm4(ah[0], &stg[wm * 32 + arow][kt * 16 + acol]);
            ldsm4(ah[1], &stg[wm * 32 + 16 + arow][kt * 16 + acol]);
#pragma unroll
            for (int jj = 0; jj < 4; jj++) {
                uint32_t bw[4];
                ldsm4(bw, &stg[128 + wn * 64 + 16 * jj + brow][kt * 16 + bcol]);
                mma_f16(acc[0][2 * jj],     ah[0], bw);
                mma_f16(acc[0][2 * jj + 1], ah[0], bw + 2);
                mma_f16(acc[1][2 * jj],     ah[1], bw);
                mma_f16(acc[1][2 * jj + 1], ah[1], bw + 2);
            }
        }
    }
}

// ---------------- QKV projection ----------------
__global__ __launch_bounds__(256, 2) void qkv_mma_kernel(
    const float* __restrict__ bq, const float* __restrict__ bk,
    const float* __restrict__ bv, const float* __restrict__ Wc)
{
    extern __shared__ __align__(16) uint16_t smg[];

    const int z = blockIdx.z;
    const int m0 = blockIdx.y * 128, n0 = blockIdx.x * 128;
    const uint16_t* W  = (z == 0) ? g_Wqh : (z == 1) ? g_Wkh : g_Wvh;
    const float* bias  = (z == 0) ? bq : (z == 1) ? bk : bv;

    float acc[2][8][4];
#pragma unroll
    for (int mt = 0; mt < 2; mt++)
#pragma unroll
        for (int nt = 0; nt < 8; nt++)
#pragma unroll
            for (int r = 0; r < 4; r++) acc[mt][nt][r] = 0.f;

    hmma_loop_16(g_Ah, W, IN_DIM, 0, IN_DIM, m0, n0, smg, acc);

    const int lane = threadIdx.x & 31, wid = threadIdx.x >> 5;
    const int wm = wid >> 1, wn = wid & 1;
    const int g = lane >> 2, tg = lane & 3;

#pragma unroll
    for (int mt = 0; mt < 2; mt++) {
#pragma unroll
        for (int nt = 0; nt < 8; nt++) {
            int m = m0 + wm * 32 + mt * 16 + g;
            int n = n0 + wn * 64 + nt * 8 + tg * 2;
            int h = n >> 6, d = n & 63;
            float v00 = acc[mt][nt][0] + bias[n];
            float v01 = acc[mt][nt][1] + bias[n + 1];
            float v10 = acc[mt][nt][2] + bias[n];
            float v11 = acc[mt][nt][3] + bias[n + 1];
            if (z == 0) {
                float qs = 0.125f * Wc[h] * 1.44269504f;   // fold scale*log2e into Q
                v00 *= qs; v01 *= qs; v10 *= qs; v11 *= qs;
                *(uint32_t*)&g_Qh[((size_t)h * S_DIM + m) * HD + d]     = cvt_h2(v00, v01);
                *(uint32_t*)&g_Qh[((size_t)h * S_DIM + m + 8) * HD + d] = cvt_h2(v10, v11);
            } else if (z == 1) {
                *(uint32_t*)&g_Kh[((size_t)h * S_DIM + m) * HD + d]     = cvt_h2(v00, v01);
                *(uint32_t*)&g_Kh[((size_t)h * S_DIM + m + 8) * HD + d] = cvt_h2(v10, v11);
            } else {
                size_t base = ((size_t)h * HD + d) * S_DIM;   // g_Vt[h][d][s]
                g_Vt[base + m]              = (uint16_t)(cvt_h2(v00, 0.f) & 0xffff);
                g_Vt[base + S_DIM + m]      = (uint16_t)(cvt_h2(v01, 0.f) & 0xffff);
                g_Vt[base + m + 8]          = (uint16_t)(cvt_h2(v10, 0.f) & 0xffff);
                g_Vt[base + S_DIM + m + 8]  = (uint16_t)(cvt_h2(v11, 0.f) & 0xffff);
            }
        }
    }
}

// ---------------- output projection, split-K (+bias +residual on half 0) ----------------
__global__ __launch_bounds__(256, 2) void out_mma_kernel(
    const float* __restrict__ emb, const float* __restrict__ bo)
{
    extern __shared__ __align__(16) uint16_t smg[];

    const int m0 = blockIdx.y * 128, n0 = blockIdx.x * 128;
    const int kz = blockIdx.z;

    float acc[2][8][4];
#pragma unroll
    for (int mt = 0; mt < 2; mt++)
#pragma unroll
        for (int nt = 0; nt < 8; nt++)
#pragma unroll
            for (int r = 0; r < 4; r++) acc[mt][nt][r] = 0.f;

    hmma_loop_16(g_Oh, g_Woh, NODE_DIM, kz * 256, kz * 256 + 256, m0, n0, smg, acc);

    const int lane = threadIdx.x & 31, wid = threadIdx.x >> 5;
    const int wm = wid >> 1, wn = wid & 1;
    const int g = lane >> 2, tg = lane & 3;
    float* dst = kz ? g_T2 : g_T;

#pragma unroll
    for (int mt = 0; mt < 2; mt++) {
#pragma unroll
        for (int nt = 0; nt < 8; nt++) {
            int m = m0 + wm * 32 + mt * 16 + g;
            int n = n0 + wn * 64 + nt * 8 + tg * 2;
            float a0 = acc[mt][nt][0], a1 = acc[mt][nt][1];
            float a2 = acc[mt][nt][2], a3 = acc[mt][nt][3];
            if (kz == 0) {
                float2 e0 = *(const float2*)&emb[(size_t)m * IN_DIM + n];
                float2 e1 = *(const float2*)&emb[(size_t)(m + 8) * IN_DIM + n];
                float2 b2 = *(const float2*)&bo[n];
                a0 += b2.x + e0.x; a1 += b2.y + e0.y;
                a2 += b2.x + e1.x; a3 += b2.y + e1.y;
            }
            *(float2*)&dst[(size_t)m * NODE_DIM + n]       = make_float2(a0, a1);
            *(float2*)&dst[(size_t)(m + 8) * NODE_DIM + n] = make_float2(a2, a3);
        }
    }
}

// ====== fp16 flash attention: 3-stage cp.async pipeline, 64-key tiles ======
// Stage block: rows 0..63 = K[key][d], rows 64..127 = Vt[d][key]. Stride 72.
#define AST 72
#define ASTAGE (128 * AST)                      // u16 per stage
#define ATTN_SMEM (3 * ASTAGE * 2)              // 55,296 B

__global__ __launch_bounds__(256, 2) void attn_kernel()
{
    extern __shared__ __align__(16) uint16_t smu[];

    const int tid = threadIdx.x;
    const int w = tid >> 5, lane = tid & 31;
    const int g = lane >> 2, tg = lane & 3;
    const int h = blockIdx.y, q0 = blockIdx.x * 128;

    const uint16_t* Qg  = g_Qh + ((size_t)h * S_DIM + q0) * HD;
    const uint16_t* Kg  = g_Kh + (size_t)h * S_DIM * HD;
    const uint16_t* Vtg = g_Vt + (size_t)h * HD * S_DIM;

    const int r0 = w * 16 + g;
    const int krow = ((lane >> 4) & 1) * 8 + (lane & 7);
    const int kcol = ((lane >> 3) & 1) * 8;

    // ---- Q fragments (pre-scaled fp16, registers for whole kernel) ----
    uint32_t qa[4][4];
#pragma unroll
    for (int kt = 0; kt < 4; kt++) {
        int c = kt * 16 + tg * 2;
        qa[kt][0] = *(const uint32_t*)&Qg[(size_t)r0 * HD + c];
        qa[kt][1] = *(const uint32_t*)&Qg[(size_t)(r0 + 8) * HD + c];
        qa[kt][2] = *(const uint32_t*)&Qg[(size_t)r0 * HD + c + 8];
        qa[kt][3] = *(const uint32_t*)&Qg[(size_t)(r0 + 8) * HD + c + 8];
    }

    float l0 = 0.f, l1 = 0.f;
    float po[8][4];
#pragma unroll
    for (int nt = 0; nt < 8; nt++)
#pragma unroll
        for (int r = 0; r < 4; r++) po[nt][r] = 0.f;

    auto cp_tile = [&](int t, int s) {
        uint16_t (*stg)[AST] = (uint16_t(*)[AST])(smu + s * ASTAGE);
#pragma unroll
        for (int i = 0; i < 2; i++) {
            int idx = tid + i * 256;                // 512: 64 rows x 8 cp16
            int kr = idx >> 3, kq = idx & 7;
            cp16(&stg[kr][kq * 8],      &Kg[(size_t)(t * 64 + kr) * HD + kq * 8]);
            cp16(&stg[64 + kr][kq * 8], &Vtg[(size_t)kr * S_DIM + t * 64 + kq * 8]);
        }
    };

    const int NT = S_DIM / 64;
    cp_tile(0, 0); CP_COMMIT();
    cp_tile(1, 1); CP_COMMIT();

    for (int t = 0; t < NT; t++) {
        CP_WAIT1();                  // tiles 0..t complete
        __syncthreads();
        int nx = t + 2;
        if (nx < NT) cp_tile(nx, nx % 3);
        CP_COMMIT();                 // one group per iteration

        uint16_t (*stg)[AST] = (uint16_t(*)[AST])(smu + (t % 3) * ASTAGE);

        // ---- contact prefetch (fp16, packed pairs) ----
        size_t gra = (size_t)(q0 + r0) * S_DIM + t * 64;
        size_t grb = gra + 8 * S_DIM;
        uint32_t ca[8], cb[8];
#pragma unroll
        for (int nt = 0; nt < 8; nt++) {
            int col = nt * 8 + tg * 2;
            ca[nt] = *(const uint32_t*)&g_Ch[gra + col];
            cb[nt] = *(const uint32_t*)&g_Ch[grb + col];
        }

        // ---- scores: S = Q K^T, f16 accumulators ----
        uint32_t sc16[8][2];
#pragma unroll
        for (int nt = 0; nt < 8; nt++) { sc16[nt][0] = 0u; sc16[nt][1] = 0u; }

#pragma unroll
        for (int kt = 0; kt < 4; kt++) {
#pragma unroll
            for (int jj = 0; jj < 4; jj++) {
                uint32_t kf[4];
                ldsm4(kf, &stg[16 * jj + krow][kt * 16 + kcol]);
                mma_f16h(sc16[2 * jj],     qa[kt], kf);
                mma_f16h(sc16[2 * jj + 1], qa[kt], kf + 2);
            }
        }

        // ---- mask * exp2, packed f16; P fragments direct ----
        uint32_t pa[4][4];
        float sa = 0.f, sb = 0.f;
#pragma unroll
        for (int kt = 0; kt < 4; kt++) {
            uint32_t p00 = h2ex2(hmul2(sc16[2 * kt][0],     ca[2 * kt]));
            uint32_t p01 = h2ex2(hmul2(sc16[2 * kt][1],     cb[2 * kt]));
            uint32_t p10 = h2ex2(hmul2(sc16[2 * kt + 1][0], ca[2 * kt + 1]));
            uint32_t p11 = h2ex2(hmul2(sc16[2 * kt + 1][1], cb[2 * kt + 1]));
            pa[kt][0] = p00; pa[kt][1] = p01; pa[kt][2] = p10; pa[kt][3] = p11;
            uint32_t s0 = hadd2(p00, p10), s1 = hadd2(p01, p11);
            float2 f0 = __half22float2(*reinterpret_cast<__half2*>(&s0));
            float2 f1 = __half22float2(*reinterpret_cast<__half2*>(&s1));
            sa += f0.x + f0.y;
            sb += f1.x + f1.y;
        }
        sa += __shfl_xor_sync(0xffffffffu, sa, 1);
        sa += __shfl_xor_sync(0xffffffffu, sa, 2);
        sb += __shfl_xor_sync(0xffffffffu, sb, 1);
        sb += __shfl_xor_sync(0xffffffffu, sb, 2);
        l0 += sa;
        l1 += sb;

        // ---- O += P V ----
#pragma unroll
        for (int kt = 0; kt < 4; kt++) {
#pragma unroll
            for (int jj = 0; jj < 4; jj++) {
                uint32_t vf[4];
                ldsm4(vf, &stg[64 + 16 * jj + krow][kt * 16 + kcol]);
                mma_f16(po[2 * jj],     pa[kt], vf);
                mma_f16(po[2 * jj + 1], pa[kt], vf + 2);
            }
        }
    }

    // ---- epilogue: O / l -> fp16 ----
    uint16_t* Og = g_Oh + ((size_t)h * S_DIM + q0) * HD;
    float ia = 1.0f / l0, ib = 1.0f / l1;
#pragma unroll
    for (int nt = 0; nt < 8; nt++) {
        int col = nt * 8 + tg * 2;
        *(uint32_t*)&Og[(size_t)r0 * HD + col] =
            cvt_h2(po[nt][0] * ia, po[nt][1] * ia);
        *(uint32_t*)&Og[(size_t)(r0 + 8) * HD + col] =
            cvt_h2(po[nt][2] * ib, po[nt][3] * ib);
    }
}

// ---------------- LayerNorm (sums the two split-K halves) ----------------
__global__ __launch_bounds__(128) void ln_kernel(
    const float* __restrict__ gamma, const float* __restrict__ beta,
    float* __restrict__ out)
{
    const int row = blockIdx.x;
    const int tid = threadIdx.x;
    float4 v  = *(const float4*)&g_T [(size_t)row * NODE_DIM + tid * 4];
    float4 v2 = *(const float4*)&g_T2[(size_t)row * NODE_DIM + tid * 4];
    v.x += v2.x; v.y += v2.y; v.z += v2.z; v.w += v2.w;
    float s = v.x + v.y + v.z + v.w;
    float ss = v.x * v.x + v.y * v.y + v.z * v.z + v.w * v.w;
#pragma unroll
    for (int off = 16; off > 0; off >>= 1) {
        s  += __shfl_xor_sync(0xffffffffu, s, off);
        ss += __shfl_xor_sync(0xffffffffu, ss, off);
    }
    __shared__ float rs[4], rss[4];
    if ((tid & 31) == 0) { rs[tid >> 5] = s; rss[tid >> 5] = ss; }
    __syncthreads();
    float S4 = rs[0] + rs[1] + rs[2] + rs[3];
    float SS4 = rss[0] + rss[1] + rss[2] + rss[3];
    float mu = S4 * (1.0f / NODE_DIM);
    float var = SS4 * (1.0f / NODE_DIM) - mu * mu;
    float rinv = rsqrtf(var + 1e-5f);
    float4 g = *(const float4*)&gamma[tid * 4];
    float4 b = *(const float4*)&beta[tid * 4];
    float4 o;
    o.x = (v.x - mu) * rinv * g.x + b.x;
    o.y = (v.y - mu) * rinv * g.y + b.y;
    o.z = (v.z - mu) * rinv * g.z + b.z;
    o.w = (v.w - mu) * rinv * g.w + b.w;
    *(float4*)&out[(size_t)row * NODE_DIM + tid * 4] = o;
}

// ---------------- launch ----------------
extern "C" void kernel_launch(void* const* d_in, const int* in_sizes, int n_in,
                              void* d_out, int out_size)
{
    const float* emb     = (const float*)d_in[0];
    const float* contact = (const float*)d_in[1];
    const float* Wq      = (const float*)d_in[2];
    const float* bq      = (const float*)d_in[3];
    const float* Wk      = (const float*)d_in[4];
    const float* bk      = (const float*)d_in[5];
    const float* Wv      = (const float*)d_in[6];
    const float* bv      = (const float*)d_in[7];
    const float* Wc      = (const float*)d_in[8];
    const float* Wo      = (const float*)d_in[9];
    const float* bo      = (const float*)d_in[10];
    const float* gamma   = (const float*)d_in[11];
    const float* beta    = (const float*)d_in[12];
    float* out = (float*)d_out;

    cudaFuncSetAttribute(qkv_mma_kernel, cudaFuncAttributeMaxDynamicSharedMemorySize,
                         GEMM_SMEM);
    cudaFuncSetAttribute(out_mma_kernel, cudaFuncAttributeMaxDynamicSharedMemorySize,
                         GEMM_SMEM);
    cudaFuncSetAttribute(attn_kernel, cudaFuncAttributeMaxDynamicSharedMemorySize,
                         ATTN_SMEM);

    prep_kernel<<<1024, 256>>>(emb, Wq, Wk, Wv, Wo, contact);
    qkv_mma_kernel<<<dim3(NODE_DIM / 128, S_DIM / 128, 3), 256, GEMM_SMEM>>>(bq, bk, bv, Wc);
    attn_kernel<<<dim3(S_DIM / 128, NH), 256, ATTN_SMEM>>>();
    out_mma_kernel<<<dim3(NODE_DIM / 128, S_DIM / 128, 2), 256, GEMM_SMEM>>>(emb, bo);
    ln_kernel<<<S_DIM, 128>>>(gamma, beta, out);
}

// round 15
// speedup vs baseline: 1.0752x; 1.0752x over previous
#include <cuda_runtime.h>
#include <cuda_fp16.h>
#include <stdint.h>
#include <math.h>

#define S_DIM  4096
#define IN_DIM 1024
#define NODE_DIM 512
#define NH 8
#define HD 64

// ---------------- scratch (no cudaMalloc allowed) ----------------
__device__ uint16_t g_Ah[S_DIM * IN_DIM];        // emb fp16
__device__ uint16_t g_Wqh[NODE_DIM * IN_DIM];
__device__ uint16_t g_Wkh[NODE_DIM * IN_DIM];
__device__ uint16_t g_Wvh[NODE_DIM * IN_DIM];
__device__ uint16_t g_Woh[NODE_DIM * NODE_DIM];
__device__ uint16_t g_Ch[S_DIM * S_DIM];         // contact fp16
__device__ uint16_t g_Qh[NH * S_DIM * HD];       // [h][s][d] fp16, pre-scaled 0.125*Wc*log2e
__device__ uint16_t g_Kh[NH * S_DIM * HD];       // [h][s][d] fp16
__device__ uint16_t g_Vt[NH * HD * S_DIM];       // [h][d][s] fp16 (transposed)
__device__ uint16_t g_Oh[NH * S_DIM * HD];       // fp16, flat == scrambled [S, H*D]
__device__ float    g_T [S_DIM * NODE_DIM];      // pre-LayerNorm, K-half 0
__device__ float    g_T2[S_DIM * NODE_DIM];      // pre-LayerNorm, K-half 1

// ---------------- helpers ----------------
__device__ __forceinline__ uint32_t cvt_h2(float lo, float hi) {
    uint32_t r;
    asm("cvt.rn.f16x2.f32 %0, %1, %2;" : "=r"(r) : "f"(hi), "f"(lo));
    return r;
}
__device__ __forceinline__ uint32_t hmul2(uint32_t a, uint32_t b) {
    uint32_t r; asm("mul.f16x2 %0, %1, %2;" : "=r"(r) : "r"(a), "r"(b)); return r;
}
__device__ __forceinline__ uint32_t hadd2(uint32_t a, uint32_t b) {
    uint32_t r; asm("add.f16x2 %0, %1, %2;" : "=r"(r) : "r"(a), "r"(b)); return r;
}
__device__ __forceinline__ uint32_t h2ex2(uint32_t a) {
    uint32_t r; asm("ex2.approx.f16x2 %0, %1;" : "=r"(r) : "r"(a)); return r;
}
__device__ __forceinline__ void mma_f16(float* d, const uint32_t* a, const uint32_t* b) {
    asm volatile(
        "mma.sync.aligned.m16n8k16.row.col.f32.f16.f16.f32 "
        "{%0,%1,%2,%3}, {%4,%5,%6,%7}, {%8,%9}, {%0,%1,%2,%3};"
        : "+f"(d[0]), "+f"(d[1]), "+f"(d[2]), "+f"(d[3])
        : "r"(a[0]), "r"(a[1]), "r"(a[2]), "r"(a[3]), "r"(b[0]), "r"(b[1]));
}
__device__ __forceinline__ void mma_f16h(uint32_t* d, const uint32_t* a, const uint32_t* b) {
    asm volatile(
        "mma.sync.aligned.m16n8k16.row.col.f16.f16.f16.f16 "
        "{%0,%1}, {%2,%3,%4,%5}, {%6,%7}, {%0,%1};"
        : "+r"(d[0]), "+r"(d[1])
        : "r"(a[0]), "r"(a[1]), "r"(a[2]), "r"(a[3]), "r"(b[0]), "r"(b[1]));
}
__device__ __forceinline__ void ldsm4(uint32_t* r, const uint16_t* p) {
    uint32_t a = (uint32_t)__cvta_generic_to_shared(p);
    asm volatile("ldmatrix.sync.aligned.m8n8.x4.shared.b16 {%0,%1,%2,%3}, [%4];"
        : "=r"(r[0]), "=r"(r[1]), "=r"(r[2]), "=r"(r[3]) : "r"(a));
}
__device__ __forceinline__ void cp16(uint16_t* dst, const uint16_t* src) {
    uint32_t a = (uint32_t)__cvta_generic_to_shared(dst);
    asm volatile("cp.async.cg.shared.global [%0], [%1], 16;" :: "r"(a), "l"(src));
}
#define CP_COMMIT() asm volatile("cp.async.commit_group;" ::: "memory")
#define CP_WAIT0()  asm volatile("cp.async.wait_group 0;" ::: "memory")
#define CP_WAIT1()  asm volatile("cp.async.wait_group 1;" ::: "memory")

// ---------------- prep: fp32 -> fp16, once (weights, emb, contact) ----------------
__global__ void prep_kernel(const float* __restrict__ emb,
                            const float* __restrict__ Wq,
                            const float* __restrict__ Wk,
                            const float* __restrict__ Wv,
                            const float* __restrict__ Wo,
                            const float* __restrict__ contact)
{
    const int t = blockIdx.x * blockDim.x + threadIdx.x;
    const int stride = gridDim.x * blockDim.x;
    for (int i = t; i < (S_DIM * IN_DIM) / 4; i += stride) {
        float4 v = ((const float4*)emb)[i];
        ((uint2*)g_Ah)[i] = make_uint2(cvt_h2(v.x, v.y), cvt_h2(v.z, v.w));
    }
    for (int i = t; i < (NODE_DIM * IN_DIM) / 4; i += stride) {
        float4 a = ((const float4*)Wq)[i];
        ((uint2*)g_Wqh)[i] = make_uint2(cvt_h2(a.x, a.y), cvt_h2(a.z, a.w));
        float4 b = ((const float4*)Wk)[i];
        ((uint2*)g_Wkh)[i] = make_uint2(cvt_h2(b.x, b.y), cvt_h2(b.z, b.w));
        float4 c = ((const float4*)Wv)[i];
        ((uint2*)g_Wvh)[i] = make_uint2(cvt_h2(c.x, c.y), cvt_h2(c.z, c.w));
    }
    for (int i = t; i < (NODE_DIM * NODE_DIM) / 4; i += stride) {
        float4 v = ((const float4*)Wo)[i];
        ((uint2*)g_Woh)[i] = make_uint2(cvt_h2(v.x, v.y), cvt_h2(v.z, v.w));
    }
    for (int i = t; i < (S_DIM * S_DIM) / 4; i += stride) {
        float4 v = ((const float4*)contact)[i];
        ((uint2*)g_Ch)[i] = make_uint2(cvt_h2(v.x, v.y), cvt_h2(v.z, v.w));
    }
}

// ======================= fp16 HMMA GEMM: K-chunk 64, cp.async double-buffer (R13) =======================
#define GST 72
#define GEMM_SMEM ((2 * 128 * GST * 2) * 2)   // 73,728 B

__device__ __forceinline__ void hmma_loop_16(
    const uint16_t* __restrict__ A, const uint16_t* __restrict__ W, int K,
    int kbeg, int kend, int m0, int n0,
    uint16_t (*sA)[GST], uint16_t (*sW)[GST],   // [2*128][GST]
    float acc[2][8][4])
{
    const int tid = threadIdx.x;
    const int wid = tid >> 5, lane = tid & 31;
    const int wm = wid >> 1, wn = wid & 1;
    const int arow = ((lane >> 3) & 1) * 8 + (lane & 7);
    const int acol = ((lane >> 4) & 1) * 8;
    const int brow = ((lane >> 4) & 1) * 8 + (lane & 7);
    const int bcol = ((lane >> 3) & 1) * 8;

    auto cp_chunk = [&](int kc, int buf) {
#pragma unroll
        for (int i = 0; i < 4; i++) {
            int idx = tid + i * 256;
            int row = idx >> 3, q = idx & 7;
            cp16(&sA[buf * 128 + row][q * 8], &A[(size_t)(m0 + row) * K + kc + q * 8]);
            cp16(&sW[buf * 128 + row][q * 8], &W[(size_t)(n0 + row) * K + kc + q * 8]);
        }
        CP_COMMIT();
    };

    cp_chunk(kbeg, 0);
    int c = 0;
    for (int kc = kbeg; kc < kend; kc += 64, c++) {
        int b = c & 1;
        CP_WAIT0();
        __syncthreads();
        if (kc + 64 < kend) cp_chunk(kc + 64, 1 - b);

#pragma unroll
        for (int kt = 0; kt < 4; kt++) {
            uint32_t ah[2][4];
            ldsm4(ah[0], &sA[b * 128 + wm * 32 + arow][kt * 16 + acol]);
            ldsm4(ah[1], &sA[b * 128 + wm * 32 + 16 + arow][kt * 16 + acol]);
#pragma unroll
            for (int jj = 0; jj < 4; jj++) {
                uint32_t bw[4];
                ldsm4(bw, &sW[b * 128 + wn * 64 + 16 * jj + brow][kt * 16 + bcol]);
                mma_f16(acc[0][2 * jj],     ah[0], bw);
                mma_f16(acc[0][2 * jj + 1], ah[0], bw + 2);
                mma_f16(acc[1][2 * jj],     ah[1], bw);
                mma_f16(acc[1][2 * jj + 1], ah[1], bw + 2);
            }
        }
    }
}

// ---------------- QKV projection ----------------
__global__ __launch_bounds__(256, 2) void qkv_mma_kernel(
    const float* __restrict__ bq, const float* __restrict__ bk,
    const float* __restrict__ bv, const float* __restrict__ Wc)
{
    extern __shared__ __align__(16) uint16_t smg[];
    uint16_t (*sA)[GST] = (uint16_t(*)[GST])smg;
    uint16_t (*sW)[GST] = (uint16_t(*)[GST])(smg + 2 * 128 * GST);

    const int z = blockIdx.z;
    const int m0 = blockIdx.y * 128, n0 = blockIdx.x * 128;
    const uint16_t* W  = (z == 0) ? g_Wqh : (z == 1) ? g_Wkh : g_Wvh;
    const float* bias  = (z == 0) ? bq : (z == 1) ? bk : bv;

    float acc[2][8][4];
#pragma unroll
    for (int mt = 0; mt < 2; mt++)
#pragma unroll
        for (int nt = 0; nt < 8; nt++)
#pragma unroll
            for (int r = 0; r < 4; r++) acc[mt][nt][r] = 0.f;

    hmma_loop_16(g_Ah, W, IN_DIM, 0, IN_DIM, m0, n0, sA, sW, acc);

    const int lane = threadIdx.x & 31, wid = threadIdx.x >> 5;
    const int wm = wid >> 1, wn = wid & 1;
    const int g = lane >> 2, tg = lane & 3;

#pragma unroll
    for (int mt = 0; mt < 2; mt++) {
#pragma unroll
        for (int nt = 0; nt < 8; nt++) {
            int m = m0 + wm * 32 + mt * 16 + g;
            int n = n0 + wn * 64 + nt * 8 + tg * 2;
            int h = n >> 6, d = n & 63;
            float v00 = acc[mt][nt][0] + bias[n];
            float v01 = acc[mt][nt][1] + bias[n + 1];
            float v10 = acc[mt][nt][2] + bias[n];
            float v11 = acc[mt][nt][3] + bias[n + 1];
            if (z == 0) {
                float qs = 0.125f * Wc[h] * 1.44269504f;
                v00 *= qs; v01 *= qs; v10 *= qs; v11 *= qs;
                *(uint32_t*)&g_Qh[((size_t)h * S_DIM + m) * HD + d]     = cvt_h2(v00, v01);
                *(uint32_t*)&g_Qh[((size_t)h * S_DIM + m + 8) * HD + d] = cvt_h2(v10, v11);
            } else if (z == 1) {
                *(uint32_t*)&g_Kh[((size_t)h * S_DIM + m) * HD + d]     = cvt_h2(v00, v01);
                *(uint32_t*)&g_Kh[((size_t)h * S_DIM + m + 8) * HD + d] = cvt_h2(v10, v11);
            } else {
                size_t base = ((size_t)h * HD + d) * S_DIM;   // g_Vt[h][d][s]
                g_Vt[base + m]              = (uint16_t)(cvt_h2(v00, 0.f) & 0xffff);
                g_Vt[base + S_DIM + m]      = (uint16_t)(cvt_h2(v01, 0.f) & 0xffff);
                g_Vt[base + m + 8]          = (uint16_t)(cvt_h2(v10, 0.f) & 0xffff);
                g_Vt[base + S_DIM + m + 8]  = (uint16_t)(cvt_h2(v11, 0.f) & 0xffff);
            }
        }
    }
}

// ---------------- output projection, split-K (+bias +residual on half 0) ----------------
__global__ __launch_bounds__(256, 2) void out_mma_kernel(
    const float* __restrict__ emb, const float* __restrict__ bo)
{
    extern __shared__ __align__(16) uint16_t smg[];
    uint16_t (*sA)[GST] = (uint16_t(*)[GST])smg;
    uint16_t (*sW)[GST] = (uint16_t(*)[GST])(smg + 2 * 128 * GST);

    const int m0 = blockIdx.y * 128, n0 = blockIdx.x * 128;
    const int kz = blockIdx.z;

    float acc[2][8][4];
#pragma unroll
    for (int mt = 0; mt < 2; mt++)
#pragma unroll
        for (int nt = 0; nt < 8; nt++)
#pragma unroll
            for (int r = 0; r < 4; r++) acc[mt][nt][r] = 0.f;

    hmma_loop_16(g_Oh, g_Woh, NODE_DIM, kz * 256, kz * 256 + 256, m0, n0, sA, sW, acc);

    const int lane = threadIdx.x & 31, wid = threadIdx.x >> 5;
    const int wm = wid >> 1, wn = wid & 1;
    const int g = lane >> 2, tg = lane & 3;
    float* dst = kz ? g_T2 : g_T;

#pragma unroll
    for (int mt = 0; mt < 2; mt++) {
#pragma unroll
        for (int nt = 0; nt < 8; nt++) {
            int m = m0 + wm * 32 + mt * 16 + g;
            int n = n0 + wn * 64 + nt * 8 + tg * 2;
            float a0 = acc[mt][nt][0], a1 = acc[mt][nt][1];
            float a2 = acc[mt][nt][2], a3 = acc[mt][nt][3];
            if (kz == 0) {
                float2 e0 = *(const float2*)&emb[(size_t)m * IN_DIM + n];
                float2 e1 = *(const float2*)&emb[(size_t)(m + 8) * IN_DIM + n];
                float2 b2 = *(const float2*)&bo[n];
                a0 += b2.x + e0.x; a1 += b2.y + e0.y;
                a2 += b2.x + e1.x; a3 += b2.y + e1.y;
            }
            *(float2*)&dst[(size_t)m * NODE_DIM + n]       = make_float2(a0, a1);
            *(float2*)&dst[(size_t)(m + 8) * NODE_DIM + n] = make_float2(a2, a3);
        }
    }
}

// ====== fp16 flash attention: 128-key tiles, 3-stage cp.async, hoisted contact ======
// Stage: K[128][AST] then Vt[64][VST].
#define AST 72
#define VST 136
#define ASTAGE (128 * AST + 64 * VST)            // u16 per stage = 17,920
#define ATTN_SMEM (3 * ASTAGE * 2)               // 107,520 B

__global__ __launch_bounds__(256, 2) void attn_kernel()
{
    extern __shared__ __align__(16) uint16_t smu[];

    const int tid = threadIdx.x;
    const int w = tid >> 5, lane = tid & 31;
    const int g = lane >> 2, tg = lane & 3;
    const int h = blockIdx.y, q0 = blockIdx.x * 128;

    const uint16_t* Qg  = g_Qh + ((size_t)h * S_DIM + q0) * HD;
    const uint16_t* Kg  = g_Kh + (size_t)h * S_DIM * HD;
    const uint16_t* Vtg = g_Vt + (size_t)h * HD * S_DIM;

    const int r0 = w * 16 + g;
    const int krow = ((lane >> 4) & 1) * 8 + (lane & 7);
    const int kcol = ((lane >> 3) & 1) * 8;

    // ---- Q fragments (pre-scaled fp16, registers for whole kernel) ----
    uint32_t qa[4][4];
#pragma unroll
    for (int kt = 0; kt < 4; kt++) {
        int c = kt * 16 + tg * 2;
        qa[kt][0] = *(const uint32_t*)&Qg[(size_t)r0 * HD + c];
        qa[kt][1] = *(const uint32_t*)&Qg[(size_t)(r0 + 8) * HD + c];
        qa[kt][2] = *(const uint32_t*)&Qg[(size_t)r0 * HD + c + 8];
        qa[kt][3] = *(const uint32_t*)&Qg[(size_t)(r0 + 8) * HD + c + 8];
    }

    float l0 = 0.f, l1 = 0.f;
    float po[8][4];
#pragma unroll
    for (int nt = 0; nt < 8; nt++)
#pragma unroll
        for (int r = 0; r < 4; r++) po[nt][r] = 0.f;

    // copy 128-key tile t into stage s (K: 128x64, Vt: 64x128)
    auto cp_tile = [&](int t, int s) {
        uint16_t* Kb = smu + s * ASTAGE;
        uint16_t* Vb = Kb + 128 * AST;
#pragma unroll
        for (int i = 0; i < 4; i++) {
            int idx = tid + i * 256;
            int kr = idx >> 3, kq = idx & 7;
            cp16(&Kb[kr * AST + kq * 8], &Kg[(size_t)(t * 128 + kr) * HD + kq * 8]);
            int vr = idx >> 4, vq = idx & 15;
            cp16(&Vb[vr * VST + vq * 8], &Vtg[(size_t)vr * S_DIM + t * 128 + vq * 8]);
        }
        CP_COMMIT();
    };

    const int NT = S_DIM / 128;
    cp_tile(0, 0);
    cp_tile(1, 1);

    for (int t = 0; t < NT; t++) {
        // ---- hoisted contact prefetch for half 0 (independent of cp.async) ----
        size_t gbase = (size_t)(q0 + r0) * S_DIM + t * 128;
        uint32_t ca[8], cb[8];
#pragma unroll
        for (int nt = 0; nt < 8; nt++) {
            int col = nt * 8 + tg * 2;
            ca[nt] = *(const uint32_t*)&g_Ch[gbase + col];
            cb[nt] = *(const uint32_t*)&g_Ch[gbase + 8 * S_DIM + col];
        }

        CP_WAIT1();                  // tiles 0..t complete
        __syncthreads();
        int nx = t + 2;
        if (nx < NT) cp_tile(nx, nx % 3);
        else CP_COMMIT();            // keep one group per iteration

        uint16_t* Kb = smu + (t % 3) * ASTAGE;
        uint16_t* Vb = Kb + 128 * AST;

#pragma unroll
        for (int hh = 0; hh < 2; hh++) {
            const int ko = hh * 64;

            if (hh == 1) {           // contact for half 1 (covered by QK MMAs below)
#pragma unroll
                for (int nt = 0; nt < 8; nt++) {
                    int col = nt * 8 + tg * 2;
                    ca[nt] = *(const uint32_t*)&g_Ch[gbase + 64 + col];
                    cb[nt] = *(const uint32_t*)&g_Ch[gbase + 8 * S_DIM + 64 + col];
                }
            }

            // ---- scores: S = Q K^T, f16 accumulators ----
            uint32_t sc16[8][2];
#pragma unroll
            for (int nt = 0; nt < 8; nt++) { sc16[nt][0] = 0u; sc16[nt][1] = 0u; }

#pragma unroll
            for (int kt = 0; kt < 4; kt++) {
#pragma unroll
                for (int jj = 0; jj < 4; jj++) {
                    uint32_t kf[4];
                    ldsm4(kf, &Kb[(ko + 16 * jj + krow) * AST + kt * 16 + kcol]);
                    mma_f16h(sc16[2 * jj],     qa[kt], kf);
                    mma_f16h(sc16[2 * jj + 1], qa[kt], kf + 2);
                }
            }

            // ---- mask * exp2, packed f16; P fragments direct ----
            uint32_t pa[4][4];
            float sa = 0.f, sb = 0.f;
#pragma unroll
            for (int kt = 0; kt < 4; kt++) {
                uint32_t p00 = h2ex2(hmul2(sc16[2 * kt][0],     ca[2 * kt]));
                uint32_t p01 = h2ex2(hmul2(sc16[2 * kt][1],     cb[2 * kt]));
                uint32_t p10 = h2ex2(hmul2(sc16[2 * kt + 1][0], ca[2 * kt + 1]));
                uint32_t p11 = h2ex2(hmul2(sc16[2 * kt + 1][1], cb[2 * kt + 1]));
                pa[kt][0] = p00; pa[kt][1] = p01; pa[kt][2] = p10; pa[kt][3] = p11;
                uint32_t s0 = hadd2(p00, p10), s1 = hadd2(p01, p11);
                float2 f0 = __half22float2(*reinterpret_cast<__half2*>(&s0));
                float2 f1 = __half22float2(*reinterpret_cast<__half2*>(&s1));
                sa += f0.x + f0.y;
                sb += f1.x + f1.y;
            }
            sa += __shfl_xor_sync(0xffffffffu, sa, 1);
            sa += __shfl_xor_sync(0xffffffffu, sa, 2);
            sb += __shfl_xor_sync(0xffffffffu, sb, 1);
            sb += __shfl_xor_sync(0xffffffffu, sb, 2);
            l0 += sa;
            l1 += sb;

            // ---- O += P V ----
#pragma unroll
            for (int kt = 0; kt < 4; kt++) {
#pragma unroll
                for (int jj = 0; jj < 4; jj++) {
                    uint32_t vf[4];
                    ldsm4(vf, &Vb[(16 * jj + krow) * VST + ko + kt * 16 + kcol]);
                    mma_f16(po[2 * jj],     pa[kt], vf);
                    mma_f16(po[2 * jj + 1], pa[kt], vf + 2);
                }
            }
        }
    }

    // ---- epilogue: O / l -> fp16 ----
    uint16_t* Og = g_Oh + ((size_t)h * S_DIM + q0) * HD;
    float ia = 1.0f / l0, ib = 1.0f / l1;
#pragma unroll
    for (int nt = 0; nt < 8; nt++) {
        int col = nt * 8 + tg * 2;
        *(uint32_t*)&Og[(size_t)r0 * HD + col] =
            cvt_h2(po[nt][0] * ia, po[nt][1] * ia);
        *(uint32_t*)&Og[(size_t)(r0 + 8) * HD + col] =
            cvt_h2(po[nt][2] * ib, po[nt][3] * ib);
    }
}

// ---------------- LayerNorm (sums the two split-K halves) ----------------
__global__ __launch_bounds__(128) void ln_kernel(
    const float* __restrict__ gamma, const float* __restrict__ beta,
    float* __restrict__ out)
{
    const int row = blockIdx.x;
    const int tid = threadIdx.x;
    float4 v  = *(const float4*)&g_T [(size_t)row * NODE_DIM + tid * 4];
    float4 v2 = *(const float4*)&g_T2[(size_t)row * NODE_DIM + tid * 4];
    v.x += v2.x; v.y += v2.y; v.z += v2.z; v.w += v2.w;
    float s = v.x + v.y + v.z + v.w;
    float ss = v.x * v.x + v.y * v.y + v.z * v.z + v.w * v.w;
#pragma unroll
    for (int off = 16; off > 0; off >>= 1) {
        s  += __shfl_xor_sync(0xffffffffu, s, off);
        ss += __shfl_xor_sync(0xffffffffu, ss, off);
    }
    __shared__ float rs[4], rss[4];
    if ((tid & 31) == 0) { rs[tid >> 5] = s; rss[tid >> 5] = ss; }
    __syncthreads();
    float S4 = rs[0] + rs[1] + rs[2] + rs[3];
    float SS4 = rss[0] + rss[1] + rss[2] + rss[3];
    float mu = S4 * (1.0f / NODE_DIM);
    float var = SS4 * (1.0f / NODE_DIM) - mu * mu;
    float rinv = rsqrtf(var + 1e-5f);
    float4 g = *(const float4*)&gamma[tid * 4];
    float4 b = *(const float4*)&beta[tid * 4];
    float4 o;
    o.x = (v.x - mu) * rinv * g.x + b.x;
    o.y = (v.y - mu) * rinv * g.y + b.y;
    o.z = (v.z - mu) * rinv * g.z + b.z;
    o.w = (v.w - mu) * rinv * g.w + b.w;
    *(float4*)&out[(size_t)row * NODE_DIM + tid * 4] = o;
}

// ---------------- launch ----------------
extern "C" void kernel_launch(void* const* d_in, const int* in_sizes, int n_in,
                              void* d_out, int out_size)
{
    const float* emb     = (const float*)d_in[0];
    const float* contact = (const float*)d_in[1];
    const float* Wq      = (const float*)d_in[2];
    const float* bq      = (const float*)d_in[3];
    const float* Wk      = (const float*)d_in[4];
    const float* bk      = (const float*)d_in[5];
    const float* Wv      = (const float*)d_in[6];
    const float* bv      = (const float*)d_in[7];
    const float* Wc      = (const float*)d_in[8];
    const float* Wo      = (const float*)d_in[9];
    const float* bo      = (const float*)d_in[10];
    const float* gamma   = (const float*)d_in[11];
    const float* beta    = (const float*)d_in[12];
    float* out = (float*)d_out;

    cudaFuncSetAttribute(qkv_mma_kernel, cudaFuncAttributeMaxDynamicSharedMemorySize,
                         GEMM_SMEM);
    cudaFuncSetAttribute(out_mma_kernel, cudaFuncAttributeMaxDynamicSharedMemorySize,
                         GEMM_SMEM);
    cudaFuncSetAttribute(attn_kernel, cudaFuncAttributeMaxDynamicSharedMemorySize,
                         ATTN_SMEM);

    prep_kernel<<<1024, 256>>>(emb, Wq, Wk, Wv, Wo, contact);
    qkv_mma_kernel<<<dim3(NODE_DIM / 128, S_DIM / 128, 3), 256, GEMM_SMEM>>>(bq, bk, bv, Wc);
    attn_kernel<<<dim3(S_DIM / 128, NH), 256, ATTN_SMEM>>>();
    out_mma_kernel<<<dim3(NODE_DIM / 128, S_DIM / 128, 2), 256, GEMM_SMEM>>>(emb, bo);
    ln_kernel<<<S_DIM, 128>>>(gamma, beta, out);
}